// round 1
// baseline (speedup 1.0000x reference)
#include <cuda_runtime.h>

namespace {

constexpr int H = 64, W = 64, C = 256;
constexpr int NDY = 21, NDX = 21;
constexpr int CC = 32;                 // channels per smem chunk
// swizzle: pi(x) = x + 20*(x>>5)  (keeps 16B alignment, kills mod-32 bank collisions)
constexpr int S1_ROW = 84;             // pi(63) = 83
constexpr int S2_ROW = 168;            // pi(103) = 163, rounded to mult of 4
constexpr int SMEM_FLOATS = CC * S1_ROW + CC * S2_ROW;

__device__ __forceinline__ int swz(int x) { return x + ((x >> 5) * 20); }

__global__ void __launch_bounds__(64)
corr_kernel(const float* __restrict__ in1, const float* __restrict__ in2,
            float* __restrict__ out)
{
    __shared__ float smem[SMEM_FLOATS];
    float* s1 = smem;                   // [CC][S1_ROW]  in1 row, swizzled
    float* s2 = smem + CC * S1_ROW;     // [CC][S2_ROW]  in2 padded row (104 wide), swizzled

    const int h   = blockIdx.x;
    const int dyi = blockIdx.y;
    const int b   = blockIdx.z;
    const int t   = threadIdx.x;

    const int h2 = h + (dyi - 10) * 2;

    // output base for (b, ch = dyi*21 + j, h, w); channel stride = H*W
    float* outp = out + (((long)b * (NDY * NDX) + (long)dyi * NDX) * H + h) * W;

    if (h2 < 0 || h2 >= H) {
        // displaced row entirely in zero padding -> outputs are zero
        for (int k = t; k < NDX * W; k += 64) {
            int j = k >> 6, w = k & 63;
            outp[(long)j * (H * W) + w] = 0.0f;
        }
        return;
    }

    // thread -> (w-tile, dx-group)
    // w-tile: 4 w values {wbase, wbase+2, wbase+4, wbase+6}, wbase = p + 8*bq
    // dx-group: 6 consecutive j starting at j0 = 5*jg (j=5,10,15 duplicated -> identical values)
    const int wt = t & 15;
    const int jg = t >> 4;
    const int p  = wt & 1;
    const int bq = wt >> 1;
    const int wbase = p + 8 * bq;
    const int j0 = jg * 5;

    int off1[4];
#pragma unroll
    for (int i = 0; i < 4; ++i) off1[i] = swz(wbase + 2 * i);
    int off2[9];
#pragma unroll
    for (int m = 0; m < 9; ++m) off2[m] = swz(wbase + 2 * j0 + 2 * m);

    float acc[6][4];
#pragma unroll
    for (int j = 0; j < 6; ++j)
#pragma unroll
        for (int i = 0; i < 4; ++i) acc[j][i] = 0.0f;

    const float* g1 = in1 + ((long)b * C * H + h)  * W;   // + c*H*W + w
    const float* g2 = in2 + ((long)b * C * H + h2) * W;

    for (int c0 = 0; c0 < C; c0 += CC) {
        // ---- stage in1 row chunk: CC x 64 floats = 512 float4, 8 per thread
#pragma unroll
        for (int it = 0; it < 8; ++it) {
            int idx = t + 64 * it;
            int c   = idx >> 4;
            int w4  = (idx & 15) << 2;
            float4 v = *(const float4*)(g1 + (long)(c0 + c) * (H * W) + w4);
            *(float4*)(s1 + c * S1_ROW + swz(w4)) = v;
        }
        // ---- stage in2 padded row chunk: CC x 104 floats = 832 float4, 13 per thread
        //      smem x-index xi = w + dx + 20; valid input cols are xi in [20,84)
#pragma unroll
        for (int it = 0; it < 13; ++it) {
            int idx = t + 64 * it;
            int c   = idx / 26;
            int q   = idx - c * 26;
            int t4  = q << 2;
            float4 v = make_float4(0.f, 0.f, 0.f, 0.f);
            if (t4 >= 20 && t4 <= 80)
                v = *(const float4*)(g2 + (long)(c0 + c) * (H * W) + (t4 - 20));
            *(float4*)(s2 + c * S2_ROW + swz(t4)) = v;
        }
        __syncthreads();

        const float* p1 = s1;
        const float* p2 = s2;
#pragma unroll 4
        for (int c = 0; c < CC; ++c) {
            float a[4], r[9];
#pragma unroll
            for (int i = 0; i < 4; ++i) a[i] = p1[off1[i]];
#pragma unroll
            for (int m = 0; m < 9; ++m) r[m] = p2[off2[m]];
#pragma unroll
            for (int j = 0; j < 6; ++j)
#pragma unroll
                for (int i = 0; i < 4; ++i)
                    acc[j][i] = fmaf(a[i], r[j + i], acc[j][i]);
            p1 += S1_ROW;
            p2 += S2_ROW;
        }
        __syncthreads();   // protect smem before next chunk's stores / final reuse
    }

    // ---- stage outputs in smem [j][w] (duplicated j's write identical values), then coalesced store
    float* sout = smem;   // reuse staging buffers (synced above)
#pragma unroll
    for (int j = 0; j < 6; ++j) {
        int jj = j0 + j;   // max 20
#pragma unroll
        for (int i = 0; i < 4; ++i)
            sout[jj * 64 + (wbase + 2 * i)] = acc[j][i];
    }
    __syncthreads();

    const float scale = 1.0f / 256.0f;
    for (int k = t; k < NDX * W; k += 64) {
        int j = k >> 6, w = k & 63;
        outp[(long)j * (H * W) + w] = sout[k] * scale;
    }
}

} // namespace

extern "C" void kernel_launch(void* const* d_in, const int* in_sizes, int n_in,
                              void* d_out, int out_size)
{
    const float* in1 = (const float*)d_in[0];
    const float* in2 = (const float*)d_in[1];
    float* out = (float*)d_out;
    dim3 grid(H, NDY, 8);
    corr_kernel<<<grid, 64>>>(in1, in2, out);
}

// round 2
// speedup vs baseline: 1.6919x; 1.6919x over previous
#include <cuda_runtime.h>

namespace {

constexpr int H = 64, W = 64, C = 256;
constexpr int NDY = 21, NDX = 21;
constexpr int CC = 16;                  // channels per smem chunk
constexpr int S1ROW = 72;               // in1 row: plane0 @0 (32 floats), plane1 @36
constexpr int S2ROW = 120;              // in2 row: plane0 @0 (52 floats), plane1 @68
constexpr int SM_FLOATS = CC * S1ROW + CC * S2ROW;  // 1152 + 1920 = 3072

__global__ void __launch_bounds__(32)
corr_kernel(const float* __restrict__ in1, const float* __restrict__ in2,
            float* __restrict__ out)
{
    __shared__ float sm[SM_FLOATS];
    float* s1 = sm;                 // [CC][2 planes of 32 (+pad)]
    float* s2 = sm + CC * S1ROW;    // [CC][2 planes of 52 (+pad)]

    const int h   = blockIdx.x;
    const int dyi = blockIdx.y;
    const int b   = blockIdx.z;
    const int t   = threadIdx.x;

    const int h2 = h + (dyi - 10) * 2;

    // out[b][dyi*21 + j][h][w]
    float* outp = out + (((long)b * (NDY * NDX) + (long)dyi * NDX) * H + h) * W;

    if (h2 < 0 || h2 >= H) {
        float4 z = make_float4(0.f, 0.f, 0.f, 0.f);
        for (int k = t; k < NDX * 16; k += 32) {       // 21 * 16 float4
            int j = k >> 4, i4 = k & 15;
            *(float4*)(outp + (long)j * (H * W) + 4 * i4) = z;
        }
        return;
    }

    // lane -> (u-tile, parity, j-group)
    const int bq = t & 3;           // u0 = 8*bq
    const int p  = (t >> 2) & 1;    // w parity
    const int jg = t >> 3;          // j0 = 5*jg
    const int u0 = bq * 8;
    const int j0 = jg * 5;

    const int offA = p * 36 + u0;            // + c*S1ROW
    const int offB = p * 68 + u0 + j0;       // + c*S2ROW

    float acc[6][8];
#pragma unroll
    for (int jj = 0; jj < 6; ++jj)
#pragma unroll
        for (int uu = 0; uu < 8; ++uu) acc[jj][uu] = 0.f;

    const float* g1 = in1 + ((long)b * C * H + h)  * W;
    const float* g2 = in2 + ((long)b * C * H + h2) * W;

    // zero-init s2 once (pad regions pos[0,10) and [42,52) stay zero forever)
    float4 z4 = make_float4(0.f, 0.f, 0.f, 0.f);
    for (int k = t; k < CC * S2ROW / 4; k += 32) ((float4*)s2)[k] = z4;

    for (int c0 = 0; c0 < C; c0 += CC) {
        __syncwarp();   // previous chunk's reads done; zero-init visible on first iter
        // ---- stage in1: CC rows x 16 float4, parity-split
#pragma unroll
        for (int it = 0; it < 8; ++it) {
            int idx = t + 32 * it;
            int c = idx >> 4, i4 = idx & 15;
            float4 v = *(const float4*)(g1 + (long)(c0 + c) * (H * W) + 4 * i4);
            *(float2*)(s1 + c * S1ROW      + 2 * i4) = make_float2(v.x, v.z);
            *(float2*)(s1 + c * S1ROW + 36 + 2 * i4) = make_float2(v.y, v.w);
        }
        // ---- stage in2: CC rows x 16 float4 -> pos 10..41 in each plane
#pragma unroll
        for (int it = 0; it < 8; ++it) {
            int idx = t + 32 * it;
            int c = idx >> 4, i4 = idx & 15;
            float4 v = *(const float4*)(g2 + (long)(c0 + c) * (H * W) + 4 * i4);
            *(float2*)(s2 + c * S2ROW + 10      + 2 * i4) = make_float2(v.x, v.z);
            *(float2*)(s2 + c * S2ROW + 68 + 10 + 2 * i4) = make_float2(v.y, v.w);
        }
        __syncwarp();

        // ---- compute: per channel 2x LDS.128 (A) + 13 scalar LDS (B) + 48 FMA
#pragma unroll 2
        for (int c = 0; c < CC; ++c) {
            const float* pa = s1 + c * S1ROW + offA;
            const float* pb = s2 + c * S2ROW + offB;
            float4 a0 = *(const float4*)pa;
            float4 a1 = *(const float4*)(pa + 4);
            float A[8] = {a0.x, a0.y, a0.z, a0.w, a1.x, a1.y, a1.z, a1.w};
            float Bv[13];
#pragma unroll
            for (int k = 0; k < 13; ++k) Bv[k] = pb[k];
#pragma unroll
            for (int jj = 0; jj < 6; ++jj)
#pragma unroll
                for (int uu = 0; uu < 8; ++uu)
                    acc[jj][uu] = fmaf(A[uu], Bv[uu + jj], acc[jj][uu]);
        }
    }

    __syncwarp();
    // ---- stage outputs [j][w] in smem (dup j's write identical values), coalesced store
    float* sout = sm;
    const float scale = 1.0f / 256.0f;
#pragma unroll
    for (int jj = 0; jj < 6; ++jj) {
        int j = j0 + jj;
#pragma unroll
        for (int uu = 0; uu < 8; ++uu)
            sout[j * 64 + p + 2 * (u0 + uu)] = acc[jj][uu] * scale;
    }
    __syncwarp();

    for (int k = t; k < NDX * 16; k += 32) {
        int j = k >> 4, i4 = k & 15;
        *(float4*)(outp + (long)j * (H * W) + 4 * i4) = *(float4*)(sout + j * 64 + 4 * i4);
    }
}

} // namespace

extern "C" void kernel_launch(void* const* d_in, const int* in_sizes, int n_in,
                              void* d_out, int out_size)
{
    const float* in1 = (const float*)d_in[0];
    const float* in2 = (const float*)d_in[1];
    float* out = (float*)d_out;
    dim3 grid(H, NDY, 8);
    corr_kernel<<<grid, 32>>>(in1, in2, out);
}